// round 1
// baseline (speedup 1.0000x reference)
#include <cuda_runtime.h>

// GeneralizedGraphDiffusion: out = prelu((sum_k theta_k*T_k * a) @ x) @ W^T + b
// N=8192, D=128, K=4.
// Fused single kernel: q never materialized in global memory.
// BM=56 rows/block -> 147 blocks = 1 wave on 148 SMs.
// f32x2 packed FMA for 2x fp32 throughput.

#define NN 8192
#define DD 128
#define BM 56
#define BJ 32
#define TPB 224
#define NTILES (NN / BJ)

__device__ __forceinline__ unsigned long long pack2(float lo, float hi) {
    unsigned long long r;
    asm("mov.b64 %0, {%1, %2};" : "=l"(r) : "f"(lo), "f"(hi));
    return r;
}
__device__ __forceinline__ void unpack2(unsigned long long v, float &lo, float &hi) {
    asm("mov.b64 {%0, %1}, %2;" : "=f"(lo), "=f"(hi) : "l"(v));
}
__device__ __forceinline__ unsigned long long fma2(unsigned long long a,
                                                   unsigned long long b,
                                                   unsigned long long c) {
    unsigned long long d;
    asm("fma.rn.f32x2 %0, %1, %2, %3;" : "=l"(d) : "l"(a), "l"(b), "l"(c));
    return d;
}

struct Pref {
    float4 pT[2][4];
    float4 pa[2];
    float4 px[5];
};

__device__ __forceinline__ void prefetch(Pref &P,
                                         const float *__restrict__ T,
                                         const float *__restrict__ a,
                                         const float *__restrict__ x,
                                         size_t rb0, size_t rb1, size_t slice,
                                         int j0, int tid) {
    const float *xsrc = x + (size_t)j0 * DD;
#pragma unroll
    for (int g = 0; g < 4; g++)
        P.px[g] = *(const float4 *)(xsrc + (tid + g * TPB) * 4);
    if (tid < 128)
        P.px[4] = *(const float4 *)(xsrc + (tid + 4 * TPB) * 4);
    const size_t o0 = rb0 + (size_t)j0;
    const size_t o1 = rb1 + (size_t)j0;
#pragma unroll
    for (int k = 0; k < 4; k++) {
        P.pT[0][k] = *(const float4 *)(T + k * slice + o0);
        P.pT[1][k] = *(const float4 *)(T + k * slice + o1);
    }
    P.pa[0] = *(const float4 *)(a + o0);
    P.pa[1] = *(const float4 *)(a + o1);
}

__device__ __forceinline__ void stage(const Pref &P, float *qs, float *xs,
                                      float th0, float th1, float th2, float th3,
                                      int row0, int jq0, int row1, int jq1, int tid) {
#pragma unroll
    for (int g = 0; g < 2; g++) {
        const int row = g ? row1 : row0;
        const int jq = g ? jq1 : jq0;
        float4 t0 = P.pT[g][0], t1 = P.pT[g][1], t2 = P.pT[g][2], t3 = P.pT[g][3];
        float4 av = P.pa[g];
        float qx = (th0 * t0.x + th1 * t1.x + th2 * t2.x + th3 * t3.x) * av.x;
        float qy = (th0 * t0.y + th1 * t1.y + th2 * t2.y + th3 * t3.y) * av.y;
        float qz = (th0 * t0.z + th1 * t1.z + th2 * t2.z + th3 * t3.z) * av.z;
        float qw = (th0 * t0.w + th1 * t1.w + th2 * t2.w + th3 * t3.w) * av.w;
        int base = (jq * 4) * 64 + row;   // qs[jj][row], row-padded stride 64
        qs[base] = qx;
        qs[base + 64] = qy;
        qs[base + 128] = qz;
        qs[base + 192] = qw;
    }
#pragma unroll
    for (int g = 0; g < 4; g++)
        *(float4 *)(xs + (tid + g * TPB) * 4) = P.px[g];
    if (tid < 128)
        *(float4 *)(xs + (tid + 4 * TPB) * 4) = P.px[4];
}

__global__ __launch_bounds__(TPB, 1)
void ggd_kernel(const float *__restrict__ theta,
                const float *__restrict__ T,
                const float *__restrict__ x,
                const float *__restrict__ a,
                const float *__restrict__ alpha,
                const float *__restrict__ W,
                const float *__restrict__ bias,
                float *__restrict__ out) {
    __shared__ __align__(16) float smem[7168];
    float *qs = smem;          // [BJ][64]   -> 2048 floats
    float *xs = smem + 2048;   // [BJ][128]  -> 4096 floats
    float *hs = smem;          // [BM][128]  -> 7168 floats (overlay after mainloop)

    const int tid = threadIdx.x;
    const int tx = tid & 15;   // column group (8 cols each)
    const int ty = tid >> 4;   // row group (4 rows each), 0..13
    const int ty4 = ty * 4;
    const int tx8 = tx * 8;
    const int i0 = blockIdx.x * BM;

    const float th0 = __ldg(theta + 0);
    const float th1 = __ldg(theta + 1);
    const float th2 = __ldg(theta + 2);
    const float th3 = __ldg(theta + 3);

    // q-construction work assignment: 448 quads = 56 rows x 8 j-quads, 2 per thread
    const int row0 = tid >> 3, jq0 = tid & 7;
    const int row1 = (tid + TPB) >> 3, jq1 = (tid + TPB) & 7;
    int gi0 = i0 + row0; if (gi0 > NN - 1) gi0 = NN - 1;
    int gi1 = i0 + row1; if (gi1 > NN - 1) gi1 = NN - 1;
    const size_t slice = (size_t)NN * NN;
    const size_t rb0 = (size_t)gi0 * NN + jq0 * 4;
    const size_t rb1 = (size_t)gi1 * NN + jq1 * 4;

    // accumulators: 4 rows x 8 cols as 4x4 f32x2 pairs
    unsigned long long acc[4][4];
#pragma unroll
    for (int m = 0; m < 4; m++)
#pragma unroll
        for (int p = 0; p < 4; p++) acc[m][p] = 0ULL;

    Pref P;
    prefetch(P, T, a, x, rb0, rb1, slice, 0, tid);

    for (int t = 0; t < NTILES; t++) {
        __syncthreads();   // previous tile fully consumed
        stage(P, qs, xs, th0, th1, th2, th3, row0, jq0, row1, jq1, tid);
        __syncthreads();   // tile visible
        if (t + 1 < NTILES)
            prefetch(P, T, a, x, rb0, rb1, slice, (t + 1) * BJ, tid);

#pragma unroll 8
        for (int jj = 0; jj < BJ; jj++) {
            float4 qv = *(const float4 *)(qs + jj * 64 + ty4);
            unsigned long long q0 = pack2(qv.x, qv.x);
            unsigned long long q1 = pack2(qv.y, qv.y);
            unsigned long long q2 = pack2(qv.z, qv.z);
            unsigned long long q3 = pack2(qv.w, qv.w);
            const ulonglong2 xa = *(const ulonglong2 *)(xs + jj * DD + tx8);
            const ulonglong2 xb = *(const ulonglong2 *)(xs + jj * DD + tx8 + 4);
            acc[0][0] = fma2(xa.x, q0, acc[0][0]);
            acc[0][1] = fma2(xa.y, q0, acc[0][1]);
            acc[0][2] = fma2(xb.x, q0, acc[0][2]);
            acc[0][3] = fma2(xb.y, q0, acc[0][3]);
            acc[1][0] = fma2(xa.x, q1, acc[1][0]);
            acc[1][1] = fma2(xa.y, q1, acc[1][1]);
            acc[1][2] = fma2(xb.x, q1, acc[1][2]);
            acc[1][3] = fma2(xb.y, q1, acc[1][3]);
            acc[2][0] = fma2(xa.x, q2, acc[2][0]);
            acc[2][1] = fma2(xa.y, q2, acc[2][1]);
            acc[2][2] = fma2(xb.x, q2, acc[2][2]);
            acc[2][3] = fma2(xb.y, q2, acc[2][3]);
            acc[3][0] = fma2(xa.x, q3, acc[3][0]);
            acc[3][1] = fma2(xa.y, q3, acc[3][1]);
            acc[3][2] = fma2(xb.x, q3, acc[3][2]);
            acc[3][3] = fma2(xb.y, q3, acc[3][3]);
        }
    }

    // ---- epilogue: PReLU -> hs (smem), then out = hs @ W^T + b ----
    __syncthreads();   // all compute reads of qs/xs done; safe to overlay hs

    float4 al0 = *(const float4 *)(alpha + tx8);
    float4 al1 = *(const float4 *)(alpha + tx8 + 4);
    float alf[8] = {al0.x, al0.y, al0.z, al0.w, al1.x, al1.y, al1.z, al1.w};

#pragma unroll
    for (int m = 0; m < 4; m++) {
        float v[8];
#pragma unroll
        for (int p = 0; p < 4; p++) unpack2(acc[m][p], v[2 * p], v[2 * p + 1]);
#pragma unroll
        for (int u = 0; u < 8; u++) v[u] = v[u] > 0.f ? v[u] : alf[u] * v[u];
        int r = ty4 + m;
        *(float4 *)(hs + r * DD + tx8) = make_float4(v[0], v[1], v[2], v[3]);
        *(float4 *)(hs + r * DD + tx8 + 4) = make_float4(v[4], v[5], v[6], v[7]);
    }
    __syncthreads();

    float oa[4][8];
#pragma unroll
    for (int m = 0; m < 4; m++)
#pragma unroll
        for (int u = 0; u < 8; u++) oa[m][u] = 0.f;

    for (int c4 = 0; c4 < DD / 4; c4++) {
        float4 wv[8];
#pragma unroll
        for (int u = 0; u < 8; u++)
            wv[u] = *(const float4 *)(W + (size_t)(tx8 + u) * DD + c4 * 4);
#pragma unroll
        for (int m = 0; m < 4; m++) {
            float4 hv = *(const float4 *)(hs + (ty4 + m) * DD + c4 * 4);
#pragma unroll
            for (int u = 0; u < 8; u++)
                oa[m][u] += hv.x * wv[u].x + hv.y * wv[u].y +
                            hv.z * wv[u].z + hv.w * wv[u].w;
        }
    }

    float4 b0 = *(const float4 *)(bias + tx8);
    float4 b1 = *(const float4 *)(bias + tx8 + 4);
#pragma unroll
    for (int m = 0; m < 4; m++) {
        int gi = i0 + ty4 + m;
        if (gi < NN) {
            float4 o0 = make_float4(oa[m][0] + b0.x, oa[m][1] + b0.y,
                                    oa[m][2] + b0.z, oa[m][3] + b0.w);
            float4 o1 = make_float4(oa[m][4] + b1.x, oa[m][5] + b1.y,
                                    oa[m][6] + b1.z, oa[m][7] + b1.w);
            *(float4 *)(out + (size_t)gi * DD + tx8) = o0;
            *(float4 *)(out + (size_t)gi * DD + tx8 + 4) = o1;
        }
    }
}

extern "C" void kernel_launch(void *const *d_in, const int *in_sizes, int n_in,
                              void *d_out, int out_size) {
    const float *theta = (const float *)d_in[0];
    const float *T     = (const float *)d_in[1];
    const float *x     = (const float *)d_in[2];
    const float *a     = (const float *)d_in[3];
    const float *alpha = (const float *)d_in[4];
    const float *W     = (const float *)d_in[5];
    const float *bias  = (const float *)d_in[6];
    float *out = (float *)d_out;
    (void)in_sizes; (void)n_in; (void)out_size;

    ggd_kernel<<<(NN + BM - 1) / BM, TPB>>>(theta, T, x, a, alpha, W, bias, out);
}